// round 3
// baseline (speedup 1.0000x reference)
#include <cuda_runtime.h>
#include <cstdint>
#include <math.h>

#define FDIM 1024

// ---------------- helpers ----------------
__device__ __forceinline__ uint32_t f2t(float f) {
    uint32_t r;
    asm("cvt.rna.tf32.f32 %0, %1;" : "=r"(r) : "f"(f));
    return r;
}

__device__ __forceinline__ void mma8(float* c, uint32_t a0, uint32_t a1, uint32_t a2, uint32_t a3,
                                     uint32_t b0, uint32_t b1) {
    asm volatile(
        "mma.sync.aligned.m16n8k8.row.col.f32.tf32.tf32.f32 "
        "{%0,%1,%2,%3},{%4,%5,%6,%7},{%8,%9},{%0,%1,%2,%3};"
        : "+f"(c[0]), "+f"(c[1]), "+f"(c[2]), "+f"(c[3])
        : "r"(a0), "r"(a1), "r"(a2), "r"(a3), "r"(b0), "r"(b1));
}

__device__ __forceinline__ uint32_t saddr(const void* p) {
    return (uint32_t)__cvta_generic_to_shared(p);
}
__device__ __forceinline__ void cp16(uint32_t s, const void* g) {
    asm volatile("cp.async.ca.shared.global [%0], [%1], 16;" :: "r"(s), "l"(g));
}
__device__ __forceinline__ void cp_commit() { asm volatile("cp.async.commit_group;"); }
__device__ __forceinline__ void cp_wait0() { asm volatile("cp.async.wait_group 0;"); }
__device__ __forceinline__ void cp_wait1() { asm volatile("cp.async.wait_group 1;"); }

__device__ __forceinline__ float softplus_f(float v) {
    return fmaxf(v, 0.f) + log1pf(__expf(-fabsf(v)));
}
__device__ __forceinline__ float sigmoid_f(float v) {
    return 1.f / (1.f + __expf(-v));
}

// =====================================================================
// Kernel AB: fused fc1+fc2 for branches 0..4 over a 64-token tile.
//   Phase 1: sH[64,320] = tf32(relu(x @ W1cat + B1cat))   (stays in smem)
//   Phase 2: for fc in 0..3 (256-feat chunks), m in 0..4:
//            out[m] = act_m(x + sH_m @ W2_m + B2_m)
// 512 threads.
// =====================================================================
#define AB_SHP 324                       // 324 % 32 == 4 -> conflict-free A frags
#define AB_SH_SZ (64 * AB_SHP)           // 20736 floats
#define A_SXP 36
#define A_SWP 328
#define A_SXSZ (64 * A_SXP)              // 2304
#define A_BUF (A_SXSZ + 32 * A_SWP)      // 12800 floats
#define AB_WP 264
#define AB_WBUF (64 * AB_WP)             // 16896 floats
#define AB_SMEM_BYTES ((AB_SH_SZ + 2 * AB_WBUF) * 4)   // 218112 B

__global__ void __launch_bounds__(512, 1)
k_ab(const float* __restrict__ x, const float* __restrict__ W1,
     const float* __restrict__ B1, const float* __restrict__ W2,
     const float* __restrict__ B2, float* __restrict__ out, int N) {
    extern __shared__ float sm[];
    float* sH = sm;
    float* p1 = sm + AB_SH_SZ;          // phase-1 double buffer / phase-2 W2 buffer (aliased)
    int tid = threadIdx.x;
    int lane = tid & 31, warp = tid >> 5;
    int g = lane >> 2, t = lane & 3;
    int wm = warp >> 2, wn = warp & 3;
    long rowBase = (long)blockIdx.x * 64;
    const float* xb = x + rowBase * FDIM;

    // ---------------- phase 1 ----------------
    float acc[40];
#pragma unroll
    for (int i = 0; i < 40; i++) acc[i] = 0.f;

    auto issue1 = [&](int it, int bi) {
        float* sx = p1 + bi * A_BUF;
        float* sw = sx + A_SXSZ;
        int k0 = it * 32;
        {
            int r = tid >> 3, seg = tid & 7;
            cp16(saddr(sx + r * A_SXP + seg * 4), xb + (long)r * FDIM + k0 + seg * 4);
        }
#pragma unroll
        for (int j = 0; j < 5; j++) {
            int idx = j * 512 + tid;
            int m = idx >> 9, rem = idx & 511;
            int k = rem >> 4, seg = rem & 15;
            cp16(saddr(sw + k * A_SWP + m * 64 + seg * 4),
                 W1 + ((long)m * FDIM + (k0 + k)) * 64 + seg * 4);
        }
        cp_commit();
    };

    const int NK = FDIM / 32;   // 32
    issue1(0, 0);
    for (int it = 0; it < NK; ++it) {
        if (it + 1 < NK) { issue1(it + 1, (it + 1) & 1); cp_wait1(); }
        else             { cp_wait0(); }
        __syncthreads();
        const float* sx = p1 + (it & 1) * A_BUF;
        const float* sw = sx + A_SXSZ;
#pragma unroll
        for (int ks = 0; ks < 4; ks++) {
            int kb = ks * 8;
            const float* ap = sx + (wm * 16 + g) * A_SXP + kb + t;
            uint32_t a0 = f2t(ap[0]), a1 = f2t(ap[8 * A_SXP]);
            uint32_t a2 = f2t(ap[4]), a3 = f2t(ap[8 * A_SXP + 4]);
#pragma unroll
            for (int nt = 0; nt < 10; nt++) {
                int c = wn * 80 + nt * 8 + g;
                uint32_t b0 = f2t(sw[(kb + t) * A_SWP + c]);
                uint32_t b1 = f2t(sw[(kb + t + 4) * A_SWP + c]);
                mma8(acc + nt * 4, a0, a1, a2, a3, b0, b1);
            }
        }
        __syncthreads();
    }

    // write H to smem, relu + bias, pre-converted to tf32 bits
    {
        int rl = wm * 16 + g;
#pragma unroll
        for (int nt = 0; nt < 10; nt++) {
            int col = wn * 80 + nt * 8 + 2 * t;
            float bb0 = B1[col], bb1 = B1[col + 1];
            float2 v;
            v.x = __uint_as_float(f2t(fmaxf(acc[nt * 4 + 0] + bb0, 0.f)));
            v.y = __uint_as_float(f2t(fmaxf(acc[nt * 4 + 1] + bb1, 0.f)));
            *(float2*)(sH + rl * AB_SHP + col) = v;
            v.x = __uint_as_float(f2t(fmaxf(acc[nt * 4 + 2] + bb0, 0.f)));
            v.y = __uint_as_float(f2t(fmaxf(acc[nt * 4 + 3] + bb1, 0.f)));
            *(float2*)(sH + (rl + 8) * AB_SHP + col) = v;
        }
    }

    // ---------------- phase 2 ----------------
    auto issue2 = [&](int it2, int bi) {
        float* sw = p1 + bi * AB_WBUF;
        int m2 = it2 % 5, fc2 = it2 / 5;
        const float* src = W2 + ((long)m2 * 64) * FDIM + (long)fc2 * 256;
#pragma unroll
        for (int j = 0; j < 8; j++) {
            int idx = j * 512 + tid;
            int h = idx >> 6, seg = idx & 63;
            cp16(saddr(sw + h * AB_WP + seg * 4), src + (long)h * FDIM + seg * 4);
        }
        cp_commit();
    };

    issue2(0, 0);
    __syncthreads();

    for (int it = 0; it < 20; ++it) {
        if (it + 1 < 20) { issue2(it + 1, (it + 1) & 1); cp_wait1(); }
        else             { cp_wait0(); }
        __syncthreads();
        int m = it % 5, fc = it / 5;
        const float* sw = p1 + (it & 1) * AB_WBUF;

        float a2[8][4];
#pragma unroll
        for (int b = 0; b < 8; b++)
#pragma unroll
            for (int c = 0; c < 4; c++) a2[b][c] = 0.f;

#pragma unroll
        for (int ks = 0; ks < 8; ks++) {
            int kb = ks * 8;
            const float* ap = sH + (wm * 16 + g) * AB_SHP + m * 64 + kb + t;
            uint32_t a0 = __float_as_uint(ap[0]);
            uint32_t a1 = __float_as_uint(ap[8 * AB_SHP]);
            uint32_t aa2 = __float_as_uint(ap[4]);
            uint32_t a3 = __float_as_uint(ap[8 * AB_SHP + 4]);
#pragma unroll
            for (int nt = 0; nt < 8; nt++) {
                int c = wn * 64 + nt * 8 + g;
                uint32_t b0 = f2t(sw[(kb + t) * AB_WP + c]);
                uint32_t b1 = f2t(sw[(kb + t + 4) * AB_WP + c]);
                mma8(a2[nt], a0, a1, aa2, a3, b0, b1);
            }
        }

        long r0 = rowBase + wm * 16 + g;
#pragma unroll
        for (int nt = 0; nt < 8; nt++) {
            int col = fc * 256 + wn * 64 + nt * 8 + 2 * t;
            float bb0 = B2[m * FDIM + col], bb1 = B2[m * FDIM + col + 1];
            float2 xv0 = *(const float2*)(x + r0 * FDIM + col);
            float2 xv1 = *(const float2*)(x + (r0 + 8) * FDIM + col);
            float v0 = a2[nt][0] + xv0.x + bb0;
            float v1 = a2[nt][1] + xv0.y + bb1;
            float v2 = a2[nt][2] + xv1.x + bb0;
            float v3 = a2[nt][3] + xv1.y + bb1;
            if (m == 3) {
                v0 = softplus_f(v0); v1 = softplus_f(v1);
                v2 = softplus_f(v2); v3 = softplus_f(v3);
            } else if (m == 4) {
                v0 = sigmoid_f(v0); v1 = sigmoid_f(v1);
                v2 = sigmoid_f(v2); v3 = sigmoid_f(v3);
            }
            float2 o;
            o.x = v0; o.y = v1;
            *(float2*)(out + ((long)m * N + r0) * FDIM + col) = o;
            o.x = v2; o.y = v3;
            *(float2*)(out + ((long)m * N + r0 + 8) * FDIM + col) = o;
        }
        __syncthreads();
    }
}

// =====================================================================
// Kernel CD: fused branch-5 MLP over a 64-token tile.
//   Phase 1: sH5[64,64] = tf32(relu(q @ W1[5] + B1[5]))   (q = out slot 2)
//   Phase 2: for fc in 0..7 (128-feat chunks):
//            out[5] = x + q + sH5 @ W2[5] + B2[5]
// 256 threads, 2 CTAs/SM.
// =====================================================================
#define CD_SHP 68                        // 68 % 32 == 4 -> conflict-free A frags
#define CD_SH_SZ (64 * CD_SHP)           // 4352 floats
#define C_SQP 36
#define C_SWP 72
#define C_BUF (64 * C_SQP + 32 * C_SWP)  // 4608 floats
#define CD_WP 136
#define CD_WBUF (64 * CD_WP)             // 8704 floats
#define CD_SMEM_BYTES ((CD_SH_SZ + 2 * CD_WBUF) * 4)   // 87040 B

__global__ void __launch_bounds__(256, 2)
k_cd(const float* __restrict__ x, const float* __restrict__ W1,
     const float* __restrict__ B1, const float* __restrict__ W2,
     const float* __restrict__ B2, float* __restrict__ out, int N) {
    extern __shared__ float sm[];
    float* sH5 = sm;
    float* p1 = sm + CD_SH_SZ;
    const float* q = out + 2ll * N * FDIM;
    int tid = threadIdx.x;
    int lane = tid & 31, warp = tid >> 5;
    int g = lane >> 2, t = lane & 3;
    long rowBase = (long)blockIdx.x * 64;

    // ---------------- phase 1 ----------------
    int pm = warp >> 1, pn = warp & 1;
    float acc[16];
#pragma unroll
    for (int i = 0; i < 16; i++) acc[i] = 0.f;

    auto issue1 = [&](int it, int bi) {
        float* sq = p1 + bi * C_BUF;
        float* sw = sq + 64 * C_SQP;
        int k0 = it * 32;
#pragma unroll
        for (int j = 0; j < 2; j++) {
            int idx = j * 256 + tid;
            int r = idx >> 3, seg = idx & 7;
            cp16(saddr(sq + r * C_SQP + seg * 4),
                 q + (rowBase + r) * FDIM + k0 + seg * 4);
        }
#pragma unroll
        for (int j = 0; j < 2; j++) {
            int idx = j * 256 + tid;
            int k = idx >> 4, seg = idx & 15;
            cp16(saddr(sw + k * C_SWP + seg * 4),
                 W1 + (5ll * FDIM + k0 + k) * 64 + seg * 4);
        }
        cp_commit();
    };

    const int NK = FDIM / 32;
    issue1(0, 0);
    for (int it = 0; it < NK; ++it) {
        if (it + 1 < NK) { issue1(it + 1, (it + 1) & 1); cp_wait1(); }
        else             { cp_wait0(); }
        __syncthreads();
        const float* sq = p1 + (it & 1) * C_BUF;
        const float* sw = sq + 64 * C_SQP;
#pragma unroll
        for (int ks = 0; ks < 4; ks++) {
            int kb = ks * 8;
            const float* ap = sq + (pm * 16 + g) * C_SQP + kb + t;
            uint32_t a0 = f2t(ap[0]), a1 = f2t(ap[8 * C_SQP]);
            uint32_t a2 = f2t(ap[4]), a3 = f2t(ap[8 * C_SQP + 4]);
#pragma unroll
            for (int nt = 0; nt < 4; nt++) {
                int c = pn * 32 + nt * 8 + g;
                uint32_t b0 = f2t(sw[(kb + t) * C_SWP + c]);
                uint32_t b1 = f2t(sw[(kb + t + 4) * C_SWP + c]);
                mma8(acc + nt * 4, a0, a1, a2, a3, b0, b1);
            }
        }
        __syncthreads();
    }

    // write H5 to smem, relu + bias, tf32 bits
    {
        int rl = pm * 16 + g;
#pragma unroll
        for (int nt = 0; nt < 4; nt++) {
            int col = pn * 32 + nt * 8 + 2 * t;
            float bb0 = B1[320 + col], bb1 = B1[320 + col + 1];
            float2 v;
            v.x = __uint_as_float(f2t(fmaxf(acc[nt * 4 + 0] + bb0, 0.f)));
            v.y = __uint_as_float(f2t(fmaxf(acc[nt * 4 + 1] + bb1, 0.f)));
            *(float2*)(sH5 + rl * CD_SHP + col) = v;
            v.x = __uint_as_float(f2t(fmaxf(acc[nt * 4 + 2] + bb0, 0.f)));
            v.y = __uint_as_float(f2t(fmaxf(acc[nt * 4 + 3] + bb1, 0.f)));
            *(float2*)(sH5 + (rl + 8) * CD_SHP + col) = v;
        }
    }

    // ---------------- phase 2 ----------------
    int wm = warp >> 1, wn = warp & 1;

    auto issue2 = [&](int fc2, int bi) {
        float* sw = p1 + bi * CD_WBUF;
        const float* src = W2 + (5ll * 64) * FDIM + (long)fc2 * 128;
#pragma unroll
        for (int j = 0; j < 8; j++) {
            int idx = j * 256 + tid;
            int h = idx >> 5, seg = idx & 31;
            cp16(saddr(sw + h * CD_WP + seg * 4), src + (long)h * FDIM + seg * 4);
        }
        cp_commit();
    };

    issue2(0, 0);
    __syncthreads();

    for (int it = 0; it < 8; ++it) {
        if (it + 1 < 8) { issue2(it + 1, (it + 1) & 1); cp_wait1(); }
        else            { cp_wait0(); }
        __syncthreads();
        const float* sw = p1 + (it & 1) * CD_WBUF;

        float a2[8][4];
#pragma unroll
        for (int b = 0; b < 8; b++)
#pragma unroll
            for (int c = 0; c < 4; c++) a2[b][c] = 0.f;

#pragma unroll
        for (int ks = 0; ks < 8; ks++) {
            int kb = ks * 8;
            const float* ap = sH5 + (wm * 16 + g) * CD_SHP + kb + t;
            uint32_t a0 = __float_as_uint(ap[0]);
            uint32_t a1 = __float_as_uint(ap[8 * CD_SHP]);
            uint32_t aa2 = __float_as_uint(ap[4]);
            uint32_t a3 = __float_as_uint(ap[8 * CD_SHP + 4]);
#pragma unroll
            for (int nt = 0; nt < 8; nt++) {
                int c = wn * 64 + nt * 8 + g;
                uint32_t b0 = f2t(sw[(kb + t) * CD_WP + c]);
                uint32_t b1 = f2t(sw[(kb + t + 4) * CD_WP + c]);
                mma8(a2[nt], a0, a1, aa2, a3, b0, b1);
            }
        }

        long r0 = rowBase + wm * 16 + g;
#pragma unroll
        for (int nt = 0; nt < 8; nt++) {
            int col = it * 128 + wn * 64 + nt * 8 + 2 * t;
            float bb0 = B2[5 * FDIM + col], bb1 = B2[5 * FDIM + col + 1];
            float2 xv0 = *(const float2*)(x + r0 * FDIM + col);
            float2 qv0 = *(const float2*)(q + r0 * FDIM + col);
            float2 xv1 = *(const float2*)(x + (r0 + 8) * FDIM + col);
            float2 qv1 = *(const float2*)(q + (r0 + 8) * FDIM + col);
            float2 o;
            o.x = a2[nt][0] + xv0.x + qv0.x + bb0;
            o.y = a2[nt][1] + xv0.y + qv0.y + bb1;
            *(float2*)(out + (5ll * N + r0) * FDIM + col) = o;
            o.x = a2[nt][2] + xv1.x + qv1.x + bb0;
            o.y = a2[nt][3] + xv1.y + qv1.y + bb1;
            *(float2*)(out + (5ll * N + r0 + 8) * FDIM + col) = o;
        }
        __syncthreads();
    }
}

// =====================================================================
extern "C" void kernel_launch(void* const* d_in, const int* in_sizes, int n_in,
                              void* d_out, int out_size) {
    const float* x  = (const float*)d_in[0];
    const float* W1 = (const float*)d_in[1];
    const float* B1 = (const float*)d_in[2];
    const float* W2 = (const float*)d_in[3];
    const float* B2 = (const float*)d_in[4];
    float* out = (float*)d_out;
    int N = in_sizes[0] / FDIM;

    cudaFuncSetAttribute(k_ab, cudaFuncAttributeMaxDynamicSharedMemorySize, AB_SMEM_BYTES);
    cudaFuncSetAttribute(k_cd, cudaFuncAttributeMaxDynamicSharedMemorySize, CD_SMEM_BYTES);

    k_ab<<<N / 64, 512, AB_SMEM_BYTES>>>(x, W1, B1, W2, B2, out, N);
    k_cd<<<N / 64, 256, CD_SMEM_BYTES>>>(x, W1, B1, W2, B2, out, N);
}

// round 8
// speedup vs baseline: 1.0439x; 1.0439x over previous
#include <cuda_runtime.h>
#include <cstdint>
#include <math.h>

#define FDIM 1024

// -------- packed tf32 weight scratch (filled by k_prep each launch) --------
static __device__ __align__(16) float2 g_W1p[163840];   // br0-4 fc1: [it32][ks4][c320][t4]
static __device__ __align__(16) float2 g_W2p[163840];   // br0-4 fc2: [p20][ks8][c256][t4]
static __device__ __align__(16) float2 g_W1p5[32768];   // br5 fc1:  [it32][ks4][c64][t4]
static __device__ __align__(16) float2 g_W2p5[32768];   // br5 fc2:  [fc8][ks8][c128][t4]

// ---------------- helpers ----------------
__device__ __forceinline__ uint32_t f2t(float f) {
    uint32_t r;
    asm("cvt.rna.tf32.f32 %0, %1;" : "=r"(r) : "f"(f));
    return r;
}
__device__ __forceinline__ void mma8(float* c, uint32_t a0, uint32_t a1, uint32_t a2, uint32_t a3,
                                     uint32_t b0, uint32_t b1) {
    asm volatile(
        "mma.sync.aligned.m16n8k8.row.col.f32.tf32.tf32.f32 "
        "{%0,%1,%2,%3},{%4,%5,%6,%7},{%8,%9},{%0,%1,%2,%3};"
        : "+f"(c[0]), "+f"(c[1]), "+f"(c[2]), "+f"(c[3])
        : "r"(a0), "r"(a1), "r"(a2), "r"(a3), "r"(b0), "r"(b1));
}
__device__ __forceinline__ uint32_t saddr(const void* p) {
    return (uint32_t)__cvta_generic_to_shared(p);
}
__device__ __forceinline__ void cp16(uint32_t s, const void* g) {
    asm volatile("cp.async.ca.shared.global [%0], [%1], 16;" :: "r"(s), "l"(g));
}
__device__ __forceinline__ void cp_commit() { asm volatile("cp.async.commit_group;"); }
__device__ __forceinline__ void cp_wait0() { asm volatile("cp.async.wait_group 0;"); }
__device__ __forceinline__ void cp_wait1() { asm volatile("cp.async.wait_group 1;"); }

__device__ __forceinline__ float softplus_f(float v) {
    return fmaxf(v, 0.f) + log1pf(__expf(-fabsf(v)));
}
__device__ __forceinline__ float sigmoid_f(float v) {
    return 1.f / (1.f + __expf(-v));
}

// =====================================================================
// k_prep: repack W1/W2 into tf32 float2-pair smem-image layouts.
// pair(ks,c,t) = ( tf32(W[kbase+ks*8+t][c]), tf32(W[kbase+ks*8+t+4][c]) )
// =====================================================================
__global__ void __launch_bounds__(256)
k_prep(const float* __restrict__ W1, const float* __restrict__ W2) {
    int i = blockIdx.x * 256 + threadIdx.x;
    if (i < 163840) {                       // W1 branches 0..4
        int t = i & 3; int r = i >> 2;
        int c = r % 320; int r2 = r / 320;
        int ks = r2 & 3; int it = r2 >> 2;
        int m = c >> 6, h = c & 63;
        int k = it * 32 + ks * 8 + t;
        float lo = W1[((long)m * 1024 + k) * 64 + h];
        float hi = W1[((long)m * 1024 + k + 4) * 64 + h];
        g_W1p[i] = make_float2(__uint_as_float(f2t(lo)), __uint_as_float(f2t(hi)));
    } else if (i < 327680) {                // W2 branches 0..4
        int j = i - 163840;
        int t = j & 3; int r = j >> 2;
        int c = r % 256; int r2 = r / 256;
        int ks = r2 & 7; int p = r2 >> 3;   // p = fc*5 + m
        int m = p % 5, fc = p / 5;
        int k = ks * 8 + t;
        int gc = fc * 256 + c;
        float lo = W2[((long)(m * 64 + k)) * 1024 + gc];
        float hi = W2[((long)(m * 64 + k + 4)) * 1024 + gc];
        g_W2p[j] = make_float2(__uint_as_float(f2t(lo)), __uint_as_float(f2t(hi)));
    } else if (i < 360448) {                // W1 branch 5
        int j = i - 327680;
        int t = j & 3; int r = j >> 2;
        int c = r & 63; int r2 = r >> 6;
        int ks = r2 & 3; int it = r2 >> 2;
        int k = it * 32 + ks * 8 + t;
        float lo = W1[(5l * 1024 + k) * 64 + c];
        float hi = W1[(5l * 1024 + k + 4) * 64 + c];
        g_W1p5[j] = make_float2(__uint_as_float(f2t(lo)), __uint_as_float(f2t(hi)));
    } else if (i < 393216) {                // W2 branch 5
        int j = i - 360448;
        int t = j & 3; int r = j >> 2;
        int c = r & 127; int r2 = r >> 7;
        int ks = r2 & 7; int fc = r2 >> 3;
        int k = ks * 8 + t;
        int gc = fc * 128 + c;
        float lo = W2[((long)(5 * 64 + k)) * 1024 + gc];
        float hi = W2[((long)(5 * 64 + k + 4)) * 1024 + gc];
        g_W2p5[j] = make_float2(__uint_as_float(f2t(lo)), __uint_as_float(f2t(hi)));
    }
}

// =====================================================================
// k_ab: fused fc1+fc2 branches 0..4 over 64-token tile. 512 threads.
//  smem (floats): sH[64*324]=20736 | pb 32768
//  phase1 stage (12544): x padded 64x36 (2304) + W1p chunk (10240)
//  phase2 stage (16384): W2p chunk
//  All loading via cp.async per-16B + group double buffering (round-3 skeleton).
// =====================================================================
#define AB_SH 324
#define AB_PB 20736
#define AB_P1 12544
#define AB_P2 16384
#define AB_SMEM ((AB_PB + 2 * AB_P2) * 4)   // 214016 B

__global__ void __launch_bounds__(512, 1)
k_ab(const float* __restrict__ x, const float* __restrict__ B1,
     const float* __restrict__ B2, float* __restrict__ out, int N) {
    extern __shared__ float sm[];
    float* sH = sm;
    float* pb = sm + AB_PB;

    int tid = threadIdx.x;
    int lane = tid & 31, warp = tid >> 5;
    int g = lane >> 2, t = lane & 3;
    int wm = warp >> 2, wn = warp & 3;
    long rowBase = (long)blockIdx.x * 64;
    const float* xb = x + rowBase * FDIM;

    // ---------------- phase 1 ----------------
    float acc[40];
#pragma unroll
    for (int i = 0; i < 40; i++) acc[i] = 0.f;

    auto issue1 = [&](int it, int s) {
        float* sx = pb + s * AB_P1;
        float* swp = sx + 2304;
        int k0 = it * 32;
        {   // x tile: 512 granules, one per thread, pitch 36 (conflict-free reads)
            int r = tid >> 3, seg = tid & 7;
            cp16(saddr(sx + r * 36 + seg * 4), xb + (long)r * FDIM + k0 + seg * 4);
        }
        // W1p chunk: 10240 floats = 2560 granules = 5 per thread, contiguous
        const float* src = (const float*)(g_W1p + (long)it * 5120);
#pragma unroll
        for (int j = 0; j < 5; j++) {
            int idx = j * 512 + tid;
            cp16(saddr(swp + idx * 4), src + idx * 4);
        }
        cp_commit();
    };

    issue1(0, 0);
    for (int it = 0; it < 32; ++it) {
        int s = it & 1;
        if (it + 1 < 32) { issue1(it + 1, s ^ 1); cp_wait1(); }
        else             { cp_wait0(); }
        __syncthreads();
        const float* sx = pb + s * AB_P1;
        const float2* wb = (const float2*)(sx + 2304);
        const float* ax = sx + (wm * 16 + g) * 36;
#pragma unroll
        for (int ks = 0; ks < 4; ks++) {
            int kb = ks * 8;
            uint32_t a0 = f2t(ax[kb + t]);
            uint32_t a1 = f2t(ax[8 * 36 + kb + t]);
            uint32_t a2 = f2t(ax[kb + t + 4]);
            uint32_t a3 = f2t(ax[8 * 36 + kb + t + 4]);
#pragma unroll
            for (int nt = 0; nt < 10; nt++) {
                int c = wn * 80 + nt * 8 + g;
                float2 bb = wb[(ks * 320 + c) * 4 + t];
                mma8(acc + nt * 4, a0, a1, a2, a3,
                     __float_as_uint(bb.x), __float_as_uint(bb.y));
            }
        }
        __syncthreads();
    }

    // prefetch phase-2 stage 0 (phase-1 buffers dead past last trailing barrier)
    {
        const float* src = (const float*)g_W2p;
#pragma unroll
        for (int j = 0; j < 8; j++) {
            int idx = j * 512 + tid;
            cp16(saddr(pb + idx * 4), src + idx * 4);
        }
        cp_commit();
    }

    // H -> smem (relu+bias, tf32 bits)
    {
        int rl = wm * 16 + g;
#pragma unroll
        for (int nt = 0; nt < 10; nt++) {
            int col = wn * 80 + nt * 8 + 2 * t;
            float bb0 = B1[col], bb1 = B1[col + 1];
            float2 v;
            v.x = __uint_as_float(f2t(fmaxf(acc[nt * 4 + 0] + bb0, 0.f)));
            v.y = __uint_as_float(f2t(fmaxf(acc[nt * 4 + 1] + bb1, 0.f)));
            *(float2*)(sH + rl * AB_SH + col) = v;
            v.x = __uint_as_float(f2t(fmaxf(acc[nt * 4 + 2] + bb0, 0.f)));
            v.y = __uint_as_float(f2t(fmaxf(acc[nt * 4 + 3] + bb1, 0.f)));
            *(float2*)(sH + (rl + 8) * AB_SH + col) = v;
        }
    }

    // ---------------- phase 2 ----------------
    auto issue2 = [&](int p, int s) {
        float* sw = pb + s * AB_P2;
        const float* src = (const float*)(g_W2p + (long)p * 8192);
#pragma unroll
        for (int j = 0; j < 8; j++) {
            int idx = j * 512 + tid;
            cp16(saddr(sw + idx * 4), src + idx * 4);
        }
        cp_commit();
    };

    for (int p = 0; p < 20; ++p) {
        int s = p & 1;
        if (p + 1 < 20) { issue2(p + 1, s ^ 1); cp_wait1(); }
        else            { cp_wait0(); }
        __syncthreads();
        int m = p % 5, fc = p / 5;
        const float2* wb = (const float2*)(pb + s * AB_P2);

        float a2c[8][4];
#pragma unroll
        for (int b = 0; b < 8; b++)
#pragma unroll
            for (int c = 0; c < 4; c++) a2c[b][c] = 0.f;

#pragma unroll
        for (int ks = 0; ks < 8; ks++) {
            const float* ap = sH + (wm * 16 + g) * AB_SH + m * 64 + ks * 8 + t;
            uint32_t a0 = __float_as_uint(ap[0]);
            uint32_t a1 = __float_as_uint(ap[8 * AB_SH]);
            uint32_t aa2 = __float_as_uint(ap[4]);
            uint32_t a3 = __float_as_uint(ap[8 * AB_SH + 4]);
#pragma unroll
            for (int nt = 0; nt < 8; nt++) {
                int c = wn * 64 + nt * 8 + g;
                float2 bb = wb[(ks * 256 + c) * 4 + t];
                mma8(a2c[nt], a0, a1, aa2, a3,
                     __float_as_uint(bb.x), __float_as_uint(bb.y));
            }
        }

        long r0 = rowBase + wm * 16 + g;
#pragma unroll
        for (int nt = 0; nt < 8; nt++) {
            int col = fc * 256 + wn * 64 + nt * 8 + 2 * t;
            float bb0 = B2[m * FDIM + col], bb1 = B2[m * FDIM + col + 1];
            float2 xv0 = *(const float2*)(x + r0 * FDIM + col);
            float2 xv1 = *(const float2*)(x + (r0 + 8) * FDIM + col);
            float v0 = a2c[nt][0] + xv0.x + bb0;
            float v1 = a2c[nt][1] + xv0.y + bb1;
            float v2 = a2c[nt][2] + xv1.x + bb0;
            float v3 = a2c[nt][3] + xv1.y + bb1;
            if (m == 3) {
                v0 = softplus_f(v0); v1 = softplus_f(v1);
                v2 = softplus_f(v2); v3 = softplus_f(v3);
            } else if (m == 4) {
                v0 = sigmoid_f(v0); v1 = sigmoid_f(v1);
                v2 = sigmoid_f(v2); v3 = sigmoid_f(v3);
            }
            float2 o;
            o.x = v0; o.y = v1;
            *(float2*)(out + ((long)m * N + r0) * FDIM + col) = o;
            o.x = v2; o.y = v3;
            *(float2*)(out + ((long)m * N + r0 + 8) * FDIM + col) = o;
        }
        __syncthreads();
    }
}

// =====================================================================
// k_cd: fused branch-5 MLP over 64-token tile. 256 threads, 2 CTA/SM.
//  smem (floats): sH5[64*68]=4352 | pb 16384
//  phase1 stage (4352): q padded 64x36 (2304) + W1p5 chunk (2048)
//  phase2 stage (8192): W2p5 chunk
// =====================================================================
#define CD_SH 68
#define CD_PB 4352
#define CD_P1 4352
#define CD_P2 8192
#define CD_SMEM ((CD_PB + 2 * CD_P2) * 4)   // 82944 B

__global__ void __launch_bounds__(256, 2)
k_cd(const float* __restrict__ x, const float* __restrict__ B1,
     const float* __restrict__ B2, float* __restrict__ out, int N) {
    extern __shared__ float sm[];
    float* sH5 = sm;
    float* pb = sm + CD_PB;
    const float* q = out + 2ll * N * FDIM;

    int tid = threadIdx.x;
    int lane = tid & 31, warp = tid >> 5;
    int g = lane >> 2, t = lane & 3;
    long rowBase = (long)blockIdx.x * 64;

    // ---------------- phase 1 ----------------
    int pm = warp >> 1, pn = warp & 1;
    float acc[16];
#pragma unroll
    for (int i = 0; i < 16; i++) acc[i] = 0.f;

    auto issue1 = [&](int it, int s) {
        float* sq = pb + s * CD_P1;
        float* swp = sq + 2304;
        int k0 = it * 32;
#pragma unroll
        for (int j = 0; j < 2; j++) {      // q tile: 512 granules, 2 per thread
            int idx = j * 256 + tid;
            int r = idx >> 3, seg = idx & 7;
            cp16(saddr(sq + r * 36 + seg * 4),
                 q + (rowBase + r) * FDIM + k0 + seg * 4);
        }
        const float* src = (const float*)(g_W1p5 + (long)it * 1024);
#pragma unroll
        for (int j = 0; j < 2; j++) {      // 2048 floats = 512 granules
            int idx = j * 256 + tid;
            cp16(saddr(swp + idx * 4), src + idx * 4);
        }
        cp_commit();
    };

    issue1(0, 0);
    for (int it = 0; it < 32; ++it) {
        int s = it & 1;
        if (it + 1 < 32) { issue1(it + 1, s ^ 1); cp_wait1(); }
        else             { cp_wait0(); }
        __syncthreads();
        const float* sq = pb + s * CD_P1;
        const float2* wb = (const float2*)(sq + 2304);
        const float* ax = sq + (pm * 16 + g) * 36;
#pragma unroll
        for (int ks = 0; ks < 4; ks++) {
            int kb = ks * 8;
            uint32_t a0 = f2t(ax[kb + t]);
            uint32_t a1 = f2t(ax[8 * 36 + kb + t]);
            uint32_t a2 = f2t(ax[kb + t + 4]);
            uint32_t a3 = f2t(ax[8 * 36 + kb + t + 4]);
#pragma unroll
            for (int nt = 0; nt < 4; nt++) {
                int c = pn * 32 + nt * 8 + g;
                float2 bb = wb[(ks * 64 + c) * 4 + t];
                mma8(acc + nt * 4, a0, a1, a2, a3,
                     __float_as_uint(bb.x), __float_as_uint(bb.y));
            }
        }
        __syncthreads();
    }

    // prefetch phase-2 stage 0
    {
        const float* src = (const float*)g_W2p5;
#pragma unroll
        for (int j = 0; j < 8; j++) {
            int idx = j * 256 + tid;
            cp16(saddr(pb + idx * 4), src + idx * 4);
        }
        cp_commit();
    }

    // H5 -> smem (relu+bias, tf32 bits)
    {
        int rl = pm * 16 + g;
#pragma unroll
        for (int nt = 0; nt < 4; nt++) {
            int col = pn * 32 + nt * 8 + 2 * t;
            float bb0 = B1[320 + col], bb1 = B1[320 + col + 1];
            float2 v;
            v.x = __uint_as_float(f2t(fmaxf(acc[nt * 4 + 0] + bb0, 0.f)));
            v.y = __uint_as_float(f2t(fmaxf(acc[nt * 4 + 1] + bb1, 0.f)));
            *(float2*)(sH5 + rl * CD_SH + col) = v;
            v.x = __uint_as_float(f2t(fmaxf(acc[nt * 4 + 2] + bb0, 0.f)));
            v.y = __uint_as_float(f2t(fmaxf(acc[nt * 4 + 3] + bb1, 0.f)));
            *(float2*)(sH5 + (rl + 8) * CD_SH + col) = v;
        }
    }

    // ---------------- phase 2 ----------------
    int wm = warp >> 1, wn = warp & 1;

    auto issue2 = [&](int p, int s) {
        float* sw = pb + s * CD_P2;
        const float* src = (const float*)(g_W2p5 + (long)p * 4096);
#pragma unroll
        for (int j = 0; j < 8; j++) {      // 8192 floats = 2048 granules
            int idx = j * 256 + tid;
            cp16(saddr(sw + idx * 4), src + idx * 4);
        }
        cp_commit();
    };

    for (int p = 0; p < 8; ++p) {
        int s = p & 1;
        if (p + 1 < 8) { issue2(p + 1, s ^ 1); cp_wait1(); }
        else           { cp_wait0(); }
        __syncthreads();
        const float2* wb = (const float2*)(pb + s * CD_P2);

        float a2c[8][4];
#pragma unroll
        for (int b = 0; b < 8; b++)
#pragma unroll
            for (int c = 0; c < 4; c++) a2c[b][c] = 0.f;

#pragma unroll
        for (int ks = 0; ks < 8; ks++) {
            const float* ap = sH5 + (wm * 16 + g) * CD_SH + ks * 8 + t;
            uint32_t a0 = __float_as_uint(ap[0]);
            uint32_t a1 = __float_as_uint(ap[8 * CD_SH]);
            uint32_t aa2 = __float_as_uint(ap[4]);
            uint32_t a3 = __float_as_uint(ap[8 * CD_SH + 4]);
#pragma unroll
            for (int nt = 0; nt < 8; nt++) {
                int c = wn * 64 + nt * 8 + g;
                float2 bb = wb[(ks * 128 + c) * 4 + t];
                mma8(a2c[nt], a0, a1, aa2, a3,
                     __float_as_uint(bb.x), __float_as_uint(bb.y));
            }
        }

        long r0 = rowBase + wm * 16 + g;
#pragma unroll
        for (int nt = 0; nt < 8; nt++) {
            int col = p * 128 + wn * 64 + nt * 8 + 2 * t;
            float bb0 = B2[5 * FDIM + col], bb1 = B2[5 * FDIM + col + 1];
            float2 xv0 = *(const float2*)(x + r0 * FDIM + col);
            float2 qv0 = *(const float2*)(q + r0 * FDIM + col);
            float2 xv1 = *(const float2*)(x + (r0 + 8) * FDIM + col);
            float2 qv1 = *(const float2*)(q + (r0 + 8) * FDIM + col);
            float2 o;
            o.x = a2c[nt][0] + xv0.x + qv0.x + bb0;
            o.y = a2c[nt][1] + xv0.y + qv0.y + bb1;
            *(float2*)(out + (5ll * N + r0) * FDIM + col) = o;
            o.x = a2c[nt][2] + xv1.x + qv1.x + bb0;
            o.y = a2c[nt][3] + xv1.y + qv1.y + bb1;
            *(float2*)(out + (5ll * N + r0 + 8) * FDIM + col) = o;
        }
        __syncthreads();
    }
}

// =====================================================================
extern "C" void kernel_launch(void* const* d_in, const int* in_sizes, int n_in,
                              void* d_out, int out_size) {
    const float* x  = (const float*)d_in[0];
    const float* W1 = (const float*)d_in[1];
    const float* B1 = (const float*)d_in[2];
    const float* W2 = (const float*)d_in[3];
    const float* B2 = (const float*)d_in[4];
    float* out = (float*)d_out;
    int N = in_sizes[0] / FDIM;

    cudaFuncSetAttribute(k_ab, cudaFuncAttributeMaxDynamicSharedMemorySize, AB_SMEM);
    cudaFuncSetAttribute(k_cd, cudaFuncAttributeMaxDynamicSharedMemorySize, CD_SMEM);

    k_prep<<<1536, 256>>>(W1, W2);
    k_ab<<<N / 64, 512, AB_SMEM>>>(x, B1, B2, out, N);
    k_cd<<<N / 64, 256, CD_SMEM>>>(x, B1, B2, out, N);
}

// round 9
// speedup vs baseline: 1.2765x; 1.2227x over previous
#include <cuda_runtime.h>
#include <cstdint>
#include <math.h>

#define FDIM 1024

// -------- packed tf32 weight scratch (filled by k_prep each launch) --------
static __device__ __align__(16) float2 g_W1p[163840];   // br0-4 fc1: [it32][ks4][c320][t4]
static __device__ __align__(16) float2 g_W2p[163840];   // br0-4 fc2: [p20][ks8][c256][t4]
static __device__ __align__(16) float2 g_W1p5[32768];   // br5 fc1:  [it32][ks4][c64][t4]
static __device__ __align__(16) float2 g_W2p5[32768];   // br5 fc2:  [fc8][ks8][c128][t4]

// ---------------- helpers ----------------
__device__ __forceinline__ uint32_t f2t(float f) {
    uint32_t r;
    asm("cvt.rna.tf32.f32 %0, %1;" : "=r"(r) : "f"(f));
    return r;
}
__device__ __forceinline__ void mma8(float* c, uint32_t a0, uint32_t a1, uint32_t a2, uint32_t a3,
                                     uint32_t b0, uint32_t b1) {
    asm volatile(
        "mma.sync.aligned.m16n8k8.row.col.f32.tf32.tf32.f32 "
        "{%0,%1,%2,%3},{%4,%5,%6,%7},{%8,%9},{%0,%1,%2,%3};"
        : "+f"(c[0]), "+f"(c[1]), "+f"(c[2]), "+f"(c[3])
        : "r"(a0), "r"(a1), "r"(a2), "r"(a3), "r"(b0), "r"(b1));
}
__device__ __forceinline__ uint32_t saddr(const void* p) {
    return (uint32_t)__cvta_generic_to_shared(p);
}
__device__ __forceinline__ void cp16(uint32_t s, const void* g) {
    asm volatile("cp.async.ca.shared.global [%0], [%1], 16;" :: "r"(s), "l"(g));
}
__device__ __forceinline__ void cp_commit() { asm volatile("cp.async.commit_group;"); }
__device__ __forceinline__ void cp_wait0() { asm volatile("cp.async.wait_group 0;"); }
__device__ __forceinline__ void cp_wait1() { asm volatile("cp.async.wait_group 1;"); }

__device__ __forceinline__ float softplus_f(float v) {
    return fmaxf(v, 0.f) + log1pf(__expf(-fabsf(v)));
}
__device__ __forceinline__ float sigmoid_f(float v) {
    return 1.f / (1.f + __expf(-v));
}

// =====================================================================
// k_prep: repack W1/W2 into tf32 float2-pair smem-image layouts.
// pair(ks,c,t) = ( tf32(W[kbase+ks*8+t][c]), tf32(W[kbase+ks*8+t+4][c]) )
// =====================================================================
__global__ void __launch_bounds__(256)
k_prep(const float* __restrict__ W1, const float* __restrict__ W2) {
    int i = blockIdx.x * 256 + threadIdx.x;
    if (i < 163840) {                       // W1 branches 0..4
        int t = i & 3; int r = i >> 2;
        int c = r % 320; int r2 = r / 320;
        int ks = r2 & 3; int it = r2 >> 2;
        int m = c >> 6, h = c & 63;
        int k = it * 32 + ks * 8 + t;
        float lo = W1[((long)m * 1024 + k) * 64 + h];
        float hi = W1[((long)m * 1024 + k + 4) * 64 + h];
        g_W1p[i] = make_float2(__uint_as_float(f2t(lo)), __uint_as_float(f2t(hi)));
    } else if (i < 327680) {                // W2 branches 0..4
        int j = i - 163840;
        int t = j & 3; int r = j >> 2;
        int c = r % 256; int r2 = r / 256;
        int ks = r2 & 7; int p = r2 >> 3;   // p = fc*5 + m
        int m = p % 5, fc = p / 5;
        int k = ks * 8 + t;
        int gc = fc * 256 + c;
        float lo = W2[((long)(m * 64 + k)) * 1024 + gc];
        float hi = W2[((long)(m * 64 + k + 4)) * 1024 + gc];
        g_W2p[j] = make_float2(__uint_as_float(f2t(lo)), __uint_as_float(f2t(hi)));
    } else if (i < 360448) {                // W1 branch 5
        int j = i - 327680;
        int t = j & 3; int r = j >> 2;
        int c = r & 63; int r2 = r >> 6;
        int ks = r2 & 3; int it = r2 >> 2;
        int k = it * 32 + ks * 8 + t;
        float lo = W1[(5l * 1024 + k) * 64 + c];
        float hi = W1[(5l * 1024 + k + 4) * 64 + c];
        g_W1p5[j] = make_float2(__uint_as_float(f2t(lo)), __uint_as_float(f2t(hi)));
    } else if (i < 393216) {                // W2 branch 5
        int j = i - 360448;
        int t = j & 3; int r = j >> 2;
        int c = r & 127; int r2 = r >> 7;
        int ks = r2 & 7; int fc = r2 >> 3;
        int k = ks * 8 + t;
        int gc = fc * 128 + c;
        float lo = W2[((long)(5 * 64 + k)) * 1024 + gc];
        float hi = W2[((long)(5 * 64 + k + 4)) * 1024 + gc];
        g_W2p5[j] = make_float2(__uint_as_float(f2t(lo)), __uint_as_float(f2t(hi)));
    }
}

// =====================================================================
// k_mlp: ONE branch (m = bid%5) over a 64-token tile (tile = bid/5).
//  256 threads, 2 CTA/SM, 83KB smem.
//  Phase 1 (warps 4Mx2N, tile 16x32): sH[64,64] = tf32(relu(x @ W1[m] + B1[m]))
//  Phase 2 (warps 2Mx4N, tile 32x32): 8 chunks of 128 feats:
//           out[m] = act_m(x + sH @ W2[m] + B2[m])
//  smem: sH 4352 fl | pb: phase1 2x4352 / phase2 2x8192 (aliased) = 16384 fl
// =====================================================================
#define MLP_SH 68
#define MLP_PB 4352
#define MLP_SMEM ((4352 + 16384) * 4)   // 82944 B

__global__ void __launch_bounds__(256, 2)
k_mlp(const float* __restrict__ x, const float* __restrict__ B1,
      const float* __restrict__ B2, float* __restrict__ out, int N) {
    extern __shared__ float sm[];
    float* sH = sm;
    float* pb = sm + MLP_PB;

    int bid = blockIdx.x;
    int m = bid % 5;
    long rowBase = (long)(bid / 5) * 64;

    int tid = threadIdx.x;
    int lane = tid & 31, warp = tid >> 5;
    int g = lane >> 2, t = lane & 3;
    const float* xb = x + rowBase * FDIM;

    // ---------------- phase 1: 64x64 = x[64,1024] @ W1[m] ----------------
    int wm = warp >> 1, wn = warp & 1;     // 4M x 2N
    float acc[16];
#pragma unroll
    for (int i = 0; i < 16; i++) acc[i] = 0.f;

    auto issue1 = [&](int it, int s) {
        float* sx = pb + s * 4352;
        float* swp = sx + 2304;
        int k0 = it * 32;
#pragma unroll
        for (int j = 0; j < 2; j++) {      // x tile: 512 granules, 2/thread
            int idx = j * 256 + tid;
            int r = idx >> 3, seg = idx & 7;
            cp16(saddr(sx + r * 36 + seg * 4), xb + (long)r * FDIM + k0 + seg * 4);
        }
        // W1p chunk for (it, m): 4 ks-pieces of 256 float2, stride 1280 float2
#pragma unroll
        for (int j = 0; j < 2; j++) {      // 512 granules, 2/thread
            int idx = j * 256 + tid;
            int ks = idx >> 7, within = idx & 127;
            const float* src = (const float*)(g_W1p + (long)(it * 4 + ks) * 1280 + m * 256);
            cp16(saddr(swp + ks * 512 + within * 4), src + within * 4);
        }
        cp_commit();
    };

    issue1(0, 0);
    for (int it = 0; it < 32; ++it) {
        int s = it & 1;
        if (it + 1 < 32) { issue1(it + 1, s ^ 1); cp_wait1(); }
        else             { cp_wait0(); }
        __syncthreads();
        const float* sx = pb + s * 4352;
        const float2* wb = (const float2*)(sx + 2304);
        const float* ax = sx + (wm * 16 + g) * 36;
#pragma unroll
        for (int ks = 0; ks < 4; ks++) {
            int kb = ks * 8;
            uint32_t a0 = f2t(ax[kb + t]);
            uint32_t a1 = f2t(ax[8 * 36 + kb + t]);
            uint32_t a2 = f2t(ax[kb + t + 4]);
            uint32_t a3 = f2t(ax[8 * 36 + kb + t + 4]);
#pragma unroll
            for (int nt = 0; nt < 4; nt++) {
                int c = wn * 32 + nt * 8 + g;
                float2 bb = wb[(ks * 64 + c) * 4 + t];
                mma8(acc + nt * 4, a0, a1, a2, a3,
                     __float_as_uint(bb.x), __float_as_uint(bb.y));
            }
        }
        __syncthreads();
    }

    // prefetch phase-2 chunk 0 (phase-1 buffers dead past trailing barrier)
    {
#pragma unroll
        for (int j = 0; j < 8; j++) {      // 2048 granules, 8/thread
            int idx = j * 256 + tid;
            int ks = idx >> 8, within = idx & 255;
            const float* src = (const float*)(g_W2p + (long)m * 8192 + ks * 1024);
            cp16(saddr(pb + ks * 1024 + within * 4), src + within * 4);
        }
        cp_commit();
    }

    // H -> smem (relu + bias, tf32 bits), pitch 68
    {
        int rl = wm * 16 + g;
#pragma unroll
        for (int nt = 0; nt < 4; nt++) {
            int col = wn * 32 + nt * 8 + 2 * t;
            float bb0 = B1[m * 64 + col], bb1 = B1[m * 64 + col + 1];
            float2 v;
            v.x = __uint_as_float(f2t(fmaxf(acc[nt * 4 + 0] + bb0, 0.f)));
            v.y = __uint_as_float(f2t(fmaxf(acc[nt * 4 + 1] + bb1, 0.f)));
            *(float2*)(sH + rl * MLP_SH + col) = v;
            v.x = __uint_as_float(f2t(fmaxf(acc[nt * 4 + 2] + bb0, 0.f)));
            v.y = __uint_as_float(f2t(fmaxf(acc[nt * 4 + 3] + bb1, 0.f)));
            *(float2*)(sH + (rl + 8) * MLP_SH + col) = v;
        }
    }

    // ---------------- phase 2: out[64,1024] in 8 chunks of 128 ----------------
    int wm2 = warp >> 2, wn2 = warp & 3;   // 2M x 4N, warp tile 32x32

    auto issue2 = [&](int jc, int s) {
        float* sw = pb + s * 8192;
        int fcb = jc >> 1, half = jc & 1;
        long base = (long)(fcb * 5 + m) * 8192 + half * 512;
#pragma unroll
        for (int j = 0; j < 8; j++) {      // 2048 granules, 8/thread
            int idx = j * 256 + tid;
            int ks = idx >> 8, within = idx & 255;
            const float* src = (const float*)(g_W2p + base + ks * 1024);
            cp16(saddr(sw + ks * 1024 + within * 4), src + within * 4);
        }
        cp_commit();
    };

    for (int jc = 0; jc < 8; ++jc) {
        int s = jc & 1;
        if (jc + 1 < 8) { issue2(jc + 1, s ^ 1); cp_wait1(); }
        else            { cp_wait0(); }
        __syncthreads();
        const float2* wb = (const float2*)(pb + s * 8192);

        float a2c[2][4][4];
#pragma unroll
        for (int a = 0; a < 2; a++)
#pragma unroll
            for (int b = 0; b < 4; b++)
#pragma unroll
                for (int c = 0; c < 4; c++) a2c[a][b][c] = 0.f;

#pragma unroll
        for (int ks = 0; ks < 8; ks++) {
            uint32_t af[2][4];
#pragma unroll
            for (int mt = 0; mt < 2; mt++) {
                const float* ap = sH + (wm2 * 32 + mt * 16 + g) * MLP_SH + ks * 8 + t;
                af[mt][0] = __float_as_uint(ap[0]);
                af[mt][1] = __float_as_uint(ap[8 * MLP_SH]);
                af[mt][2] = __float_as_uint(ap[4]);
                af[mt][3] = __float_as_uint(ap[8 * MLP_SH + 4]);
            }
#pragma unroll
            for (int nt = 0; nt < 4; nt++) {
                int c = wn2 * 32 + nt * 8 + g;
                float2 bb = wb[(ks * 128 + c) * 4 + t];
                uint32_t b0 = __float_as_uint(bb.x), b1 = __float_as_uint(bb.y);
                mma8(a2c[0][nt], af[0][0], af[0][1], af[0][2], af[0][3], b0, b1);
                mma8(a2c[1][nt], af[1][0], af[1][1], af[1][2], af[1][3], b0, b1);
            }
        }

#pragma unroll
        for (int mt = 0; mt < 2; mt++) {
            long r0 = rowBase + wm2 * 32 + mt * 16 + g;
#pragma unroll
            for (int nt = 0; nt < 4; nt++) {
                int col = jc * 128 + wn2 * 32 + nt * 8 + 2 * t;
                float bb0 = B2[m * FDIM + col], bb1 = B2[m * FDIM + col + 1];
                float2 xv0 = *(const float2*)(x + r0 * FDIM + col);
                float2 xv1 = *(const float2*)(x + (r0 + 8) * FDIM + col);
                float v0 = a2c[mt][nt][0] + xv0.x + bb0;
                float v1 = a2c[mt][nt][1] + xv0.y + bb1;
                float v2 = a2c[mt][nt][2] + xv1.x + bb0;
                float v3 = a2c[mt][nt][3] + xv1.y + bb1;
                if (m == 3) {
                    v0 = softplus_f(v0); v1 = softplus_f(v1);
                    v2 = softplus_f(v2); v3 = softplus_f(v3);
                } else if (m == 4) {
                    v0 = sigmoid_f(v0); v1 = sigmoid_f(v1);
                    v2 = sigmoid_f(v2); v3 = sigmoid_f(v3);
                }
                float2 o;
                o.x = v0; o.y = v1;
                *(float2*)(out + ((long)m * N + r0) * FDIM + col) = o;
                o.x = v2; o.y = v3;
                *(float2*)(out + ((long)m * N + r0 + 8) * FDIM + col) = o;
            }
        }
        __syncthreads();
    }
}

// =====================================================================
// k_mlp5: branch 5 (memory MLP). Same structure; A = q (out slot 2),
// epilogue adds x + q. W1p5/W2p5 chunks are fully contiguous.
// =====================================================================
__global__ void __launch_bounds__(256, 2)
k_mlp5(const float* __restrict__ x, const float* __restrict__ B1,
       const float* __restrict__ B2, float* __restrict__ out, int N) {
    extern __shared__ float sm[];
    float* sH = sm;
    float* pb = sm + MLP_PB;
    const float* q = out + 2ll * N * FDIM;

    long rowBase = (long)blockIdx.x * 64;
    int tid = threadIdx.x;
    int lane = tid & 31, warp = tid >> 5;
    int g = lane >> 2, t = lane & 3;
    const float* qb = q + rowBase * FDIM;

    // ---------------- phase 1 ----------------
    int wm = warp >> 1, wn = warp & 1;
    float acc[16];
#pragma unroll
    for (int i = 0; i < 16; i++) acc[i] = 0.f;

    auto issue1 = [&](int it, int s) {
        float* sx = pb + s * 4352;
        float* swp = sx + 2304;
        int k0 = it * 32;
#pragma unroll
        for (int j = 0; j < 2; j++) {
            int idx = j * 256 + tid;
            int r = idx >> 3, seg = idx & 7;
            cp16(saddr(sx + r * 36 + seg * 4), qb + (long)r * FDIM + k0 + seg * 4);
        }
        const float* src = (const float*)(g_W1p5 + (long)it * 1024);
#pragma unroll
        for (int j = 0; j < 2; j++) {
            int idx = j * 256 + tid;
            cp16(saddr(swp + idx * 4), src + idx * 4);
        }
        cp_commit();
    };

    issue1(0, 0);
    for (int it = 0; it < 32; ++it) {
        int s = it & 1;
        if (it + 1 < 32) { issue1(it + 1, s ^ 1); cp_wait1(); }
        else             { cp_wait0(); }
        __syncthreads();
        const float* sx = pb + s * 4352;
        const float2* wb = (const float2*)(sx + 2304);
        const float* ax = sx + (wm * 16 + g) * 36;
#pragma unroll
        for (int ks = 0; ks < 4; ks++) {
            int kb = ks * 8;
            uint32_t a0 = f2t(ax[kb + t]);
            uint32_t a1 = f2t(ax[8 * 36 + kb + t]);
            uint32_t a2 = f2t(ax[kb + t + 4]);
            uint32_t a3 = f2t(ax[8 * 36 + kb + t + 4]);
#pragma unroll
            for (int nt = 0; nt < 4; nt++) {
                int c = wn * 32 + nt * 8 + g;
                float2 bb = wb[(ks * 64 + c) * 4 + t];
                mma8(acc + nt * 4, a0, a1, a2, a3,
                     __float_as_uint(bb.x), __float_as_uint(bb.y));
            }
        }
        __syncthreads();
    }

    // prefetch phase-2 chunk 0
    {
        const float* src = (const float*)g_W2p5;
#pragma unroll
        for (int j = 0; j < 8; j++) {
            int idx = j * 256 + tid;
            cp16(saddr(pb + idx * 4), src + idx * 4);
        }
        cp_commit();
    }

    // H5 -> smem
    {
        int rl = wm * 16 + g;
#pragma unroll
        for (int nt = 0; nt < 4; nt++) {
            int col = wn * 32 + nt * 8 + 2 * t;
            float bb0 = B1[320 + col], bb1 = B1[320 + col + 1];
            float2 v;
            v.x = __uint_as_float(f2t(fmaxf(acc[nt * 4 + 0] + bb0, 0.f)));
            v.y = __uint_as_float(f2t(fmaxf(acc[nt * 4 + 1] + bb1, 0.f)));
            *(float2*)(sH + rl * MLP_SH + col) = v;
            v.x = __uint_as_float(f2t(fmaxf(acc[nt * 4 + 2] + bb0, 0.f)));
            v.y = __uint_as_float(f2t(fmaxf(acc[nt * 4 + 3] + bb1, 0.f)));
            *(float2*)(sH + (rl + 8) * MLP_SH + col) = v;
        }
    }

    // ---------------- phase 2 ----------------
    int wm2 = warp >> 2, wn2 = warp & 3;

    auto issue2 = [&](int jc, int s) {
        float* sw = pb + s * 8192;
        const float* src = (const float*)(g_W2p5 + (long)jc * 4096);
#pragma unroll
        for (int j = 0; j < 8; j++) {
            int idx = j * 256 + tid;
            cp16(saddr(sw + idx * 4), src + idx * 4);
        }
        cp_commit();
    };

    for (int jc = 0; jc < 8; ++jc) {
        int s = jc & 1;
        if (jc + 1 < 8) { issue2(jc + 1, s ^ 1); cp_wait1(); }
        else            { cp_wait0(); }
        __syncthreads();
        const float2* wb = (const float2*)(pb + s * 8192);

        float a2c[2][4][4];
#pragma unroll
        for (int a = 0; a < 2; a++)
#pragma unroll
            for (int b = 0; b < 4; b++)
#pragma unroll
                for (int c = 0; c < 4; c++) a2c[a][b][c] = 0.f;

#pragma unroll
        for (int ks = 0; ks < 8; ks++) {
            uint32_t af[2][4];
#pragma unroll
            for (int mt = 0; mt < 2; mt++) {
                const float* ap = sH + (wm2 * 32 + mt * 16 + g) * MLP_SH + ks * 8 + t;
                af[mt][0] = __float_as_uint(ap[0]);
                af[mt][1] = __float_as_uint(ap[8 * MLP_SH]);
                af[mt][2] = __float_as_uint(ap[4]);
                af[mt][3] = __float_as_uint(ap[8 * MLP_SH + 4]);
            }
#pragma unroll
            for (int nt = 0; nt < 4; nt++) {
                int c = wn2 * 32 + nt * 8 + g;
                float2 bb = wb[(ks * 128 + c) * 4 + t];
                uint32_t b0 = __float_as_uint(bb.x), b1 = __float_as_uint(bb.y);
                mma8(a2c[0][nt], af[0][0], af[0][1], af[0][2], af[0][3], b0, b1);
                mma8(a2c[1][nt], af[1][0], af[1][1], af[1][2], af[1][3], b0, b1);
            }
        }

#pragma unroll
        for (int mt = 0; mt < 2; mt++) {
            long r0 = rowBase + wm2 * 32 + mt * 16 + g;
#pragma unroll
            for (int nt = 0; nt < 4; nt++) {
                int col = jc * 128 + wn2 * 32 + nt * 8 + 2 * t;
                float bb0 = B2[5 * FDIM + col], bb1 = B2[5 * FDIM + col + 1];
                float2 xv0 = *(const float2*)(x + r0 * FDIM + col);
                float2 qv0 = *(const float2*)(q + r0 * FDIM + col);
                float2 xv1 = *(const float2*)(x + (r0 + 8) * FDIM + col);
                float2 qv1 = *(const float2*)(q + (r0 + 8) * FDIM + col);
                float2 o;
                o.x = a2c[mt][nt][0] + xv0.x + qv0.x + bb0;
                o.y = a2c[mt][nt][1] + xv0.y + qv0.y + bb1;
                *(float2*)(out + (5ll * N + r0) * FDIM + col) = o;
                o.x = a2c[mt][nt][2] + xv1.x + qv1.x + bb0;
                o.y = a2c[mt][nt][3] + xv1.y + qv1.y + bb1;
                *(float2*)(out + (5ll * N + r0 + 8) * FDIM + col) = o;
            }
        }
        __syncthreads();
    }
}

// =====================================================================
extern "C" void kernel_launch(void* const* d_in, const int* in_sizes, int n_in,
                              void* d_out, int out_size) {
    const float* x  = (const float*)d_in[0];
    const float* W1 = (const float*)d_in[1];
    const float* B1 = (const float*)d_in[2];
    const float* W2 = (const float*)d_in[3];
    const float* B2 = (const float*)d_in[4];
    float* out = (float*)d_out;
    int N = in_sizes[0] / FDIM;

    cudaFuncSetAttribute(k_mlp,  cudaFuncAttributeMaxDynamicSharedMemorySize, MLP_SMEM);
    cudaFuncSetAttribute(k_mlp5, cudaFuncAttributeMaxDynamicSharedMemorySize, MLP_SMEM);

    k_prep<<<1536, 256>>>(W1, W2);
    k_mlp<<<(N / 64) * 5, 256, MLP_SMEM>>>(x, B1, B2, out, N);
    k_mlp5<<<N / 64, 256, MLP_SMEM>>>(x, B1, B2, out, N);
}

// round 13
// speedup vs baseline: 1.3039x; 1.0215x over previous
#include <cuda_runtime.h>
#include <cstdint>
#include <math.h>

#define FDIM 1024

// -------- packed tf32 weight scratch (filled by k_prep each launch) --------
static __device__ __align__(16) float2 g_W1p[163840];   // br0-4 fc1: [it32][ks4][c320][t4]
static __device__ __align__(16) float2 g_W2p[163840];   // br0-4 fc2: [p20][ks8][c256][t4]
static __device__ __align__(16) float2 g_W1p5[32768];   // br5 fc1:  [it32][ks4][c64][t4]
static __device__ __align__(16) float2 g_W2p5[32768];   // br5 fc2:  [fc8][ks8][c128][t4]

// ---------------- helpers ----------------
__device__ __forceinline__ uint32_t f2t(float f) {
    uint32_t r;
    asm("cvt.rna.tf32.f32 %0, %1;" : "=r"(r) : "f"(f));
    return r;
}
__device__ __forceinline__ void mma8(float* c, uint32_t a0, uint32_t a1, uint32_t a2, uint32_t a3,
                                     uint32_t b0, uint32_t b1) {
    asm volatile(
        "mma.sync.aligned.m16n8k8.row.col.f32.tf32.tf32.f32 "
        "{%0,%1,%2,%3},{%4,%5,%6,%7},{%8,%9},{%0,%1,%2,%3};"
        : "+f"(c[0]), "+f"(c[1]), "+f"(c[2]), "+f"(c[3])
        : "r"(a0), "r"(a1), "r"(a2), "r"(a3), "r"(b0), "r"(b1));
}
__device__ __forceinline__ uint32_t saddr(const void* p) {
    return (uint32_t)__cvta_generic_to_shared(p);
}
__device__ __forceinline__ void cp16(uint32_t s, const void* g) {
    asm volatile("cp.async.ca.shared.global [%0], [%1], 16;" :: "r"(s), "l"(g));
}
__device__ __forceinline__ void cp_commit() { asm volatile("cp.async.commit_group;"); }
__device__ __forceinline__ void cp_wait0() { asm volatile("cp.async.wait_group 0;"); }
__device__ __forceinline__ void cp_wait1() { asm volatile("cp.async.wait_group 1;"); }
__device__ __forceinline__ void cp_wait2() { asm volatile("cp.async.wait_group 2;"); }

__device__ __forceinline__ float softplus_f(float v) {
    return fmaxf(v, 0.f) + log1pf(__expf(-fabsf(v)));
}
__device__ __forceinline__ float sigmoid_f(float v) {
    return 1.f / (1.f + __expf(-v));
}

// =====================================================================
// k_prep: repack W1/W2 into tf32 float2-pair smem-image layouts.
// pair(ks,c,t) = ( tf32(W[kbase+ks*8+t][c]), tf32(W[kbase+ks*8+t+4][c]) )
// =====================================================================
__global__ void __launch_bounds__(256)
k_prep(const float* __restrict__ W1, const float* __restrict__ W2) {
    int i = blockIdx.x * 256 + threadIdx.x;
    if (i < 163840) {                       // W1 branches 0..4
        int t = i & 3; int r = i >> 2;
        int c = r % 320; int r2 = r / 320;
        int ks = r2 & 3; int it = r2 >> 2;
        int m = c >> 6, h = c & 63;
        int k = it * 32 + ks * 8 + t;
        float lo = W1[((long)m * 1024 + k) * 64 + h];
        float hi = W1[((long)m * 1024 + k + 4) * 64 + h];
        g_W1p[i] = make_float2(__uint_as_float(f2t(lo)), __uint_as_float(f2t(hi)));
    } else if (i < 327680) {                // W2 branches 0..4
        int j = i - 163840;
        int t = j & 3; int r = j >> 2;
        int c = r % 256; int r2 = r / 256;
        int ks = r2 & 7; int p = r2 >> 3;   // p = fc*5 + m
        int m = p % 5, fc = p / 5;
        int k = ks * 8 + t;
        int gc = fc * 256 + c;
        float lo = W2[((long)(m * 64 + k)) * 1024 + gc];
        float hi = W2[((long)(m * 64 + k + 4)) * 1024 + gc];
        g_W2p[j] = make_float2(__uint_as_float(f2t(lo)), __uint_as_float(f2t(hi)));
    } else if (i < 360448) {                // W1 branch 5
        int j = i - 327680;
        int t = j & 3; int r = j >> 2;
        int c = r & 63; int r2 = r >> 6;
        int ks = r2 & 3; int it = r2 >> 2;
        int k = it * 32 + ks * 8 + t;
        float lo = W1[(5l * 1024 + k) * 64 + c];
        float hi = W1[(5l * 1024 + k + 4) * 64 + c];
        g_W1p5[j] = make_float2(__uint_as_float(f2t(lo)), __uint_as_float(f2t(hi)));
    } else if (i < 393216) {                // W2 branch 5
        int j = i - 360448;
        int t = j & 3; int r = j >> 2;
        int c = r & 127; int r2 = r >> 7;
        int ks = r2 & 7; int fc = r2 >> 3;
        int k = ks * 8 + t;
        int gc = fc * 128 + c;
        float lo = W2[((long)(5 * 64 + k)) * 1024 + gc];
        float hi = W2[((long)(5 * 64 + k + 4)) * 1024 + gc];
        g_W2p5[j] = make_float2(__uint_as_float(f2t(lo)), __uint_as_float(f2t(hi)));
    }
}

// =====================================================================
// k_mlp: ONE branch (m = bid%5) over a 64-token tile (tile = bid/5).
//  256 threads, 2 CTA/SM, 83KB smem.
//  Phase 1 (warps 4Mx2N): 3-stage cp.async ring, sH[64,64] = relu(x@W1[m]+B1)
//  Phase 2 (warps 2Mx4N): 8 chunks of 128 feats, x prefetched to regs.
//  smem: sH 4352 fl | pb: phase1 3x4352=13056 / phase2 2x8192=16384 (aliased)
// =====================================================================
#define MLP_SH 68
#define MLP_PB 4352
#define MLP_SMEM ((4352 + 16384) * 4)   // 82944 B

__global__ void __launch_bounds__(256, 2)
k_mlp(const float* __restrict__ x, const float* __restrict__ B1,
      const float* __restrict__ B2, float* __restrict__ out, int N) {
    extern __shared__ float sm[];
    float* sH = sm;
    float* pb = sm + MLP_PB;

    int bid = blockIdx.x;
    int m = bid % 5;
    long rowBase = (long)(bid / 5) * 64;

    int tid = threadIdx.x;
    int lane = tid & 31, warp = tid >> 5;
    int g = lane >> 2, t = lane & 3;
    const float* xb = x + rowBase * FDIM;

    // ---------------- phase 1: 64x64 = x[64,1024] @ W1[m], 3-stage ----------------
    int wm = warp >> 1, wn = warp & 1;     // 4M x 2N
    float acc[16];
#pragma unroll
    for (int i = 0; i < 16; i++) acc[i] = 0.f;

    auto issue1 = [&](int it, int s) {
        float* sx = pb + s * 4352;
        float* swp = sx + 2304;
        int k0 = it * 32;
#pragma unroll
        for (int j = 0; j < 2; j++) {      // x tile: 512 granules, 2/thread
            int idx = j * 256 + tid;
            int r = idx >> 3, seg = idx & 7;
            cp16(saddr(sx + r * 36 + seg * 4), xb + (long)r * FDIM + k0 + seg * 4);
        }
        // W1p chunk for (it, m): 4 ks-pieces of 256 float2, stride 1280 float2
#pragma unroll
        for (int j = 0; j < 2; j++) {      // 512 granules, 2/thread
            int idx = j * 256 + tid;
            int ks = idx >> 7, within = idx & 127;
            const float* src = (const float*)(g_W1p + (long)(it * 4 + ks) * 1280 + m * 256);
            cp16(saddr(swp + ks * 512 + within * 4), src + within * 4);
        }
        cp_commit();
    };

    issue1(0, 0); issue1(1, 1);
    for (int it = 0; it < 32; ++it) {
        int s = it % 3;
        if (it + 2 < 32) issue1(it + 2, (it + 2) % 3);
        if (it < 30) cp_wait2(); else if (it == 30) cp_wait1(); else cp_wait0();
        __syncthreads();
        const float* sx = pb + s * 4352;
        const float2* wb = (const float2*)(sx + 2304);
        const float* ax = sx + (wm * 16 + g) * 36;
#pragma unroll
        for (int ks = 0; ks < 4; ks++) {
            int kb = ks * 8;
            uint32_t a0 = f2t(ax[kb + t]);
            uint32_t a1 = f2t(ax[8 * 36 + kb + t]);
            uint32_t a2 = f2t(ax[kb + t + 4]);
            uint32_t a3 = f2t(ax[8 * 36 + kb + t + 4]);
#pragma unroll
            for (int nt = 0; nt < 4; nt++) {
                int c = wn * 32 + nt * 8 + g;
                float2 bb = wb[(ks * 64 + c) * 4 + t];
                mma8(acc + nt * 4, a0, a1, a2, a3,
                     __float_as_uint(bb.x), __float_as_uint(bb.y));
            }
        }
        __syncthreads();
    }

    // prefetch phase-2 chunk 0 (phase-1 buffers dead past trailing barrier)
    {
#pragma unroll
        for (int j = 0; j < 8; j++) {      // 2048 granules, 8/thread
            int idx = j * 256 + tid;
            int ks = idx >> 8, within = idx & 255;
            const float* src = (const float*)(g_W2p + (long)m * 8192 + ks * 1024);
            cp16(saddr(pb + ks * 1024 + within * 4), src + within * 4);
        }
        cp_commit();
    }

    // H -> smem (relu + bias, tf32 bits), pitch 68
    {
        int rl = wm * 16 + g;
#pragma unroll
        for (int nt = 0; nt < 4; nt++) {
            int col = wn * 32 + nt * 8 + 2 * t;
            float bb0 = B1[m * 64 + col], bb1 = B1[m * 64 + col + 1];
            float2 v;
            v.x = __uint_as_float(f2t(fmaxf(acc[nt * 4 + 0] + bb0, 0.f)));
            v.y = __uint_as_float(f2t(fmaxf(acc[nt * 4 + 1] + bb1, 0.f)));
            *(float2*)(sH + rl * MLP_SH + col) = v;
            v.x = __uint_as_float(f2t(fmaxf(acc[nt * 4 + 2] + bb0, 0.f)));
            v.y = __uint_as_float(f2t(fmaxf(acc[nt * 4 + 3] + bb1, 0.f)));
            *(float2*)(sH + (rl + 8) * MLP_SH + col) = v;
        }
    }

    // ---------------- phase 2: out[64,1024] in 8 chunks of 128 ----------------
    int wm2 = warp >> 2, wn2 = warp & 3;   // 2M x 4N, warp tile 32x32

    auto issue2 = [&](int jc, int s) {
        float* sw = pb + s * 8192;
        int fcb = jc >> 1, half = jc & 1;
        long base = (long)(fcb * 5 + m) * 8192 + half * 512;
#pragma unroll
        for (int j = 0; j < 8; j++) {      // 2048 granules, 8/thread
            int idx = j * 256 + tid;
            int ks = idx >> 8, within = idx & 255;
            const float* src = (const float*)(g_W2p + base + ks * 1024);
            cp16(saddr(sw + ks * 1024 + within * 4), src + within * 4);
        }
        cp_commit();
    };

    for (int jc = 0; jc < 8; ++jc) {
        int s = jc & 1;
        if (jc + 1 < 8) { issue2(jc + 1, s ^ 1); cp_wait1(); }
        else            { cp_wait0(); }
        __syncthreads();
        const float2* wb = (const float2*)(pb + s * 8192);

        // prefetch this chunk's x residuals into registers (hidden by MMAs)
        float2 xv[2][4][2];
#pragma unroll
        for (int mt = 0; mt < 2; mt++) {
            long r0 = rowBase + wm2 * 32 + mt * 16 + g;
#pragma unroll
            for (int nt = 0; nt < 4; nt++) {
                int col = jc * 128 + wn2 * 32 + nt * 8 + 2 * t;
                xv[mt][nt][0] = *(const float2*)(x + r0 * FDIM + col);
                xv[mt][nt][1] = *(const float2*)(x + (r0 + 8) * FDIM + col);
            }
        }

        float a2c[2][4][4];
#pragma unroll
        for (int a = 0; a < 2; a++)
#pragma unroll
            for (int b = 0; b < 4; b++)
#pragma unroll
                for (int c = 0; c < 4; c++) a2c[a][b][c] = 0.f;

#pragma unroll
        for (int ks = 0; ks < 8; ks++) {
            uint32_t af[2][4];
#pragma unroll
            for (int mt = 0; mt < 2; mt++) {
                const float* ap = sH + (wm2 * 32 + mt * 16 + g) * MLP_SH + ks * 8 + t;
                af[mt][0] = __float_as_uint(ap[0]);
                af[mt][1] = __float_as_uint(ap[8 * MLP_SH]);
                af[mt][2] = __float_as_uint(ap[4]);
                af[mt][3] = __float_as_uint(ap[8 * MLP_SH + 4]);
            }
#pragma unroll
            for (int nt = 0; nt < 4; nt++) {
                int c = wn2 * 32 + nt * 8 + g;
                float2 bb = wb[(ks * 128 + c) * 4 + t];
                uint32_t b0 = __float_as_uint(bb.x), b1 = __float_as_uint(bb.y);
                mma8(a2c[0][nt], af[0][0], af[0][1], af[0][2], af[0][3], b0, b1);
                mma8(a2c[1][nt], af[1][0], af[1][1], af[1][2], af[1][3], b0, b1);
            }
        }

#pragma unroll
        for (int mt = 0; mt < 2; mt++) {
            long r0 = rowBase + wm2 * 32 + mt * 16 + g;
#pragma unroll
            for (int nt = 0; nt < 4; nt++) {
                int col = jc * 128 + wn2 * 32 + nt * 8 + 2 * t;
                float bb0 = B2[m * FDIM + col], bb1 = B2[m * FDIM + col + 1];
                float v0 = a2c[mt][nt][0] + xv[mt][nt][0].x + bb0;
                float v1 = a2c[mt][nt][1] + xv[mt][nt][0].y + bb1;
                float v2 = a2c[mt][nt][2] + xv[mt][nt][1].x + bb0;
                float v3 = a2c[mt][nt][3] + xv[mt][nt][1].y + bb1;
                if (m == 3) {
                    v0 = softplus_f(v0); v1 = softplus_f(v1);
                    v2 = softplus_f(v2); v3 = softplus_f(v3);
                } else if (m == 4) {
                    v0 = sigmoid_f(v0); v1 = sigmoid_f(v1);
                    v2 = sigmoid_f(v2); v3 = sigmoid_f(v3);
                }
                float2 o;
                o.x = v0; o.y = v1;
                *(float2*)(out + ((long)m * N + r0) * FDIM + col) = o;
                o.x = v2; o.y = v3;
                *(float2*)(out + ((long)m * N + r0 + 8) * FDIM + col) = o;
            }
        }
        __syncthreads();
    }
}

// =====================================================================
// k_mlp5: branch 5 (memory MLP). Same structure; A = q (out slot 2),
// epilogue adds x + q (both prefetched to regs, summed on arrival).
// =====================================================================
__global__ void __launch_bounds__(256, 2)
k_mlp5(const float* __restrict__ x, const float* __restrict__ B1,
       const float* __restrict__ B2, float* __restrict__ out, int N) {
    extern __shared__ float sm[];
    float* sH = sm;
    float* pb = sm + MLP_PB;
    const float* q = out + 2ll * N * FDIM;

    long rowBase = (long)blockIdx.x * 64;
    int tid = threadIdx.x;
    int lane = tid & 31, warp = tid >> 5;
    int g = lane >> 2, t = lane & 3;
    const float* qb = q + rowBase * FDIM;

    // ---------------- phase 1: 3-stage ----------------
    int wm = warp >> 1, wn = warp & 1;
    float acc[16];
#pragma unroll
    for (int i = 0; i < 16; i++) acc[i] = 0.f;

    auto issue1 = [&](int it, int s) {
        float* sx = pb + s * 4352;
        float* swp = sx + 2304;
        int k0 = it * 32;
#pragma unroll
        for (int j = 0; j < 2; j++) {
            int idx = j * 256 + tid;
            int r = idx >> 3, seg = idx & 7;
            cp16(saddr(sx + r * 36 + seg * 4), qb + (long)r * FDIM + k0 + seg * 4);
        }
        const float* src = (const float*)(g_W1p5 + (long)it * 1024);
#pragma unroll
        for (int j = 0; j < 2; j++) {
            int idx = j * 256 + tid;
            cp16(saddr(swp + idx * 4), src + idx * 4);
        }
        cp_commit();
    };

    issue1(0, 0); issue1(1, 1);
    for (int it = 0; it < 32; ++it) {
        int s = it % 3;
        if (it + 2 < 32) issue1(it + 2, (it + 2) % 3);
        if (it < 30) cp_wait2(); else if (it == 30) cp_wait1(); else cp_wait0();
        __syncthreads();
        const float* sx = pb + s * 4352;
        const float2* wb = (const float2*)(sx + 2304);
        const float* ax = sx + (wm * 16 + g) * 36;
#pragma unroll
        for (int ks = 0; ks < 4; ks++) {
            int kb = ks * 8;
            uint32_t a0 = f2t(ax[kb + t]);
            uint32_t a1 = f2t(ax[8 * 36 + kb + t]);
            uint32_t a2 = f2t(ax[kb + t + 4]);
            uint32_t a3 = f2t(ax[8 * 36 + kb + t + 4]);
#pragma unroll
            for (int nt = 0; nt < 4; nt++) {
                int c = wn * 32 + nt * 8 + g;
                float2 bb = wb[(ks * 64 + c) * 4 + t];
                mma8(acc + nt * 4, a0, a1, a2, a3,
                     __float_as_uint(bb.x), __float_as_uint(bb.y));
            }
        }
        __syncthreads();
    }

    // prefetch phase-2 chunk 0
    {
        const float* src = (const float*)g_W2p5;
#pragma unroll
        for (int j = 0; j < 8; j++) {
            int idx = j * 256 + tid;
            cp16(saddr(pb + idx * 4), src + idx * 4);
        }
        cp_commit();
    }

    // H5 -> smem
    {
        int rl = wm * 16 + g;
#pragma unroll
        for (int nt = 0; nt < 4; nt++) {
            int col = wn * 32 + nt * 8 + 2 * t;
            float bb0 = B1[320 + col], bb1 = B1[320 + col + 1];
            float2 v;
            v.x = __uint_as_float(f2t(fmaxf(acc[nt * 4 + 0] + bb0, 0.f)));
            v.y = __uint_as_float(f2t(fmaxf(acc[nt * 4 + 1] + bb1, 0.f)));
            *(float2*)(sH + rl * MLP_SH + col) = v;
            v.x = __uint_as_float(f2t(fmaxf(acc[nt * 4 + 2] + bb0, 0.f)));
            v.y = __uint_as_float(f2t(fmaxf(acc[nt * 4 + 3] + bb1, 0.f)));
            *(float2*)(sH + (rl + 8) * MLP_SH + col) = v;
        }
    }

    // ---------------- phase 2 ----------------
    int wm2 = warp >> 2, wn2 = warp & 3;

    auto issue2 = [&](int jc, int s) {
        float* sw = pb + s * 8192;
        const float* src = (const float*)(g_W2p5 + (long)jc * 4096);
#pragma unroll
        for (int j = 0; j < 8; j++) {
            int idx = j * 256 + tid;
            cp16(saddr(sw + idx * 4), src + idx * 4);
        }
        cp_commit();
    };

    for (int jc = 0; jc < 8; ++jc) {
        int s = jc & 1;
        if (jc + 1 < 8) { issue2(jc + 1, s ^ 1); cp_wait1(); }
        else            { cp_wait0(); }
        __syncthreads();
        const float2* wb = (const float2*)(pb + s * 8192);

        // prefetch x+q residual sums into registers
        float2 xv[2][4][2];
#pragma unroll
        for (int mt = 0; mt < 2; mt++) {
            long r0 = rowBase + wm2 * 32 + mt * 16 + g;
#pragma unroll
            for (int nt = 0; nt < 4; nt++) {
                int col = jc * 128 + wn2 * 32 + nt * 8 + 2 * t;
                float2 a0 = *(const float2*)(x + r0 * FDIM + col);
                float2 b0 = *(const float2*)(q + r0 * FDIM + col);
                float2 a1 = *(const float2*)(x + (r0 + 8) * FDIM + col);
                float2 b1 = *(const float2*)(q + (r0 + 8) * FDIM + col);
                xv[mt][nt][0] = make_float2(a0.x + b0.x, a0.y + b0.y);
                xv[mt][nt][1] = make_float2(a1.x + b1.x, a1.y + b1.y);
            }
        }

        float a2c[2][4][4];
#pragma unroll
        for (int a = 0; a < 2; a++)
#pragma unroll
            for (int b = 0; b < 4; b++)
#pragma unroll
                for (int c = 0; c < 4; c++) a2c[a][b][c] = 0.f;

#pragma unroll
        for (int ks = 0; ks < 8; ks++) {
            uint32_t af[2][4];
#pragma unroll
            for (int mt = 0; mt < 2; mt++) {
                const float* ap = sH + (wm2 * 32 + mt * 16 + g) * MLP_SH + ks * 8 + t;
                af[mt][0] = __float_as_uint(ap[0]);
                af[mt][1] = __float_as_uint(ap[8 * MLP_SH]);
                af[mt][2] = __float_as_uint(ap[4]);
                af[mt][3] = __float_as_uint(ap[8 * MLP_SH + 4]);
            }
#pragma unroll
            for (int nt = 0; nt < 4; nt++) {
                int c = wn2 * 32 + nt * 8 + g;
                float2 bb = wb[(ks * 128 + c) * 4 + t];
                uint32_t b0 = __float_as_uint(bb.x), b1 = __float_as_uint(bb.y);
                mma8(a2c[0][nt], af[0][0], af[0][1], af[0][2], af[0][3], b0, b1);
                mma8(a2c[1][nt], af[1][0], af[1][1], af[1][2], af[1][3], b0, b1);
            }
        }

#pragma unroll
        for (int mt = 0; mt < 2; mt++) {
            long r0 = rowBase + wm2 * 32 + mt * 16 + g;
#pragma unroll
            for (int nt = 0; nt < 4; nt++) {
                int col = jc * 128 + wn2 * 32 + nt * 8 + 2 * t;
                float bb0 = B2[5 * FDIM + col], bb1 = B2[5 * FDIM + col + 1];
                float2 o;
                o.x = a2c[mt][nt][0] + xv[mt][nt][0].x + bb0;
                o.y = a2c[mt][nt][1] + xv[mt][nt][0].y + bb1;
                *(float2*)(out + (5ll * N + r0) * FDIM + col) = o;
                o.x = a2c[mt][nt][2] + xv[mt][nt][1].x + bb0;
                o.y = a2c[mt][nt][3] + xv[mt][nt][1].y + bb1;
                *(float2*)(out + (5ll * N + r0 + 8) * FDIM + col) = o;
            }
        }
        __syncthreads();
    }
}

// =====================================================================
extern "C" void kernel_launch(void* const* d_in, const int* in_sizes, int n_in,
                              void* d_out, int out_size) {
    const float* x  = (const float*)d_in[0];
    const float* W1 = (const float*)d_in[1];
    const float* B1 = (const float*)d_in[2];
    const float* W2 = (const float*)d_in[3];
    const float* B2 = (const float*)d_in[4];
    float* out = (float*)d_out;
    int N = in_sizes[0] / FDIM;

    cudaFuncSetAttribute(k_mlp,  cudaFuncAttributeMaxDynamicSharedMemorySize, MLP_SMEM);
    cudaFuncSetAttribute(k_mlp5, cudaFuncAttributeMaxDynamicSharedMemorySize, MLP_SMEM);

    k_prep<<<1536, 256>>>(W1, W2);
    k_mlp<<<(N / 64) * 5, 256, MLP_SMEM>>>(x, B1, B2, out, N);
    k_mlp5<<<N / 64, 256, MLP_SMEM>>>(x, B1, B2, out, N);
}